// round 13
// baseline (speedup 1.0000x reference)
#include <cuda_runtime.h>
#include <cstdint>
#include <math.h>

#define OUTSZ 260
#define IMGW  2048
#define IMGH  2048
#define TAPS  6
#define NBOX  10
#define NWARP 9
#define NTHR  (NWARP * 32)
#define WWIN  800                      // floats per warp data segment
#define TAPFLOATS (NTHR * 12)          // per-thread 48B tap slot
#define SMEM_FLOATS (TAPFLOATS + NWARP * WWIN)

struct __align__(16) Tap6 {
    float w[TAPS];
    int   j[TAPS];
};

__device__ Tap6  g_tapv[NBOX][OUTSZ];   // vertical: j = absolute image row
__device__ Tap6  g_taph[NBOX][OUTSZ];   // horizontal: w premult (norm*validity), j = crop-local float idx
__device__ int   g_gbeg[NBOX];          // x0*3
__device__ int   g_cw[NBOX];            // cw

// Lanczos3 weights for 6 integer-spaced taps (frac in [0,1)) via angle addition.
__device__ __forceinline__ void lanczos6(float frac, float* w) {
    const float sn = sinpif(frac);
    const float su = sinpif(frac * (1.0f / 3.0f));
    const float cu = cospif(frac * (1.0f / 3.0f));
    const float R3 = 0.8660254037844386f;
    float s3[TAPS];
    s3[0] = fmaf(su, -0.5f,  cu *  R3);
    s3[1] = fmaf(su,  0.5f,  cu *  R3);
    s3[2] = su;
    s3[3] = fmaf(su,  0.5f,  cu * -R3);
    s3[4] = fmaf(su, -0.5f,  cu * -R3);
    s3[5] = -su;
    const float C = 3.0f / (3.14159265358979323846f * 3.14159265358979323846f);
#pragma unroll
    for (int a = 0; a < TAPS; a++) {
        float d = frac + (float)(2 - a);
        float sgn = (a & 1) ? -sn : sn;
        float val = sgn * s3[a] * C / (d * d);
        w[a] = (fabsf(d) < 1e-8f) ? 1.0f : val;
    }
}

__global__ void precompute_taps(const float* __restrict__ scores,
                                const float* __restrict__ boxes) {
    const int box = blockIdx.x;     // 0..9
    const int p   = threadIdx.x;    // 0..259

    const float b0 = boxes[box * 4 + 0];
    const float b1 = boxes[box * 4 + 1];
    const float b2 = boxes[box * 4 + 2];
    const float b3 = boxes[box * 4 + 3];
    // XLA f32->s32 convert truncates toward zero; values non-negative here.
    const int y0 = (int)(b0 * (float)IMGH);
    const int x0 = (int)(b1 * (float)IMGW);
    const int y1 = (int)(b2 * (float)IMGH);
    const int x1 = (int)(b3 * (float)IMGW);
    const int ch = max(y1 - y0, 1);
    const int cw = max(x1 - x0, 1);

    const bool valid = (scores[0] >= 0.8f) && (scores[box] >= 0.8f) &&
                       (b1 >= 0.0f) && (b3 <= 1.0f);

    {   // vertical taps for output row p
        const float src = ((float)p + 0.5f) * ((float)ch / (float)OUTSZ) - 0.5f;
        const float f = floorf(src);
        const int base = (int)f - 2;
        Tap6 t;
        lanczos6(src - f, t.w);
        float s = t.w[0] + t.w[1] + t.w[2] + t.w[3] + t.w[4] + t.w[5];
        float inv = 1.0f / s;
#pragma unroll
        for (int a = 0; a < TAPS; a++) {
            t.w[a] *= inv;
            t.j[a] = min(max(base + a, 0), ch - 1) + y0;
        }
        g_tapv[box][p] = t;
    }

    {   // horizontal taps for output col p (weights folded with validity)
        const float src = ((float)p + 0.5f) * ((float)cw / (float)OUTSZ) - 0.5f;
        const float f = floorf(src);
        const int base = (int)f - 2;
        Tap6 t;
        lanczos6(src - f, t.w);
        float s = t.w[0] + t.w[1] + t.w[2] + t.w[3] + t.w[4] + t.w[5];
        float inv = valid ? (1.0f / s) : 0.0f;
#pragma unroll
        for (int b = 0; b < TAPS; b++) {
            t.w[b] *= inv;
            t.j[b] = min(max(base + b, 0), cw - 1) * 3;   // crop-local float index
        }
        g_taph[box][p] = t;
    }

    if (p == 0) {
        g_gbeg[box] = x0 * 3;
        g_cw[box]   = cw;
    }
}

__global__ __launch_bounds__(NTHR, 4)
void crop_resize_kernel(const float* __restrict__ img,
                        float* __restrict__ out) {
    // PDL: wait until the precompute kernel's writes are visible.
    asm volatile("griddepcontrol.wait;" ::: "memory");

    const int p    = blockIdx.x;        // output row 0..259
    const int box  = blockIdx.y;        // 0..9
    const int w    = threadIdx.x >> 5;  // warp 0..8
    const int lane = threadIdx.x & 31;
    const int qlo  = w * 32;
    const int q    = qlo + lane;

    extern __shared__ float smem[];
    float* tapslot = smem + threadIdx.x * 12;     // this thread's 48B tap copy
    float* seg     = smem + TAPFLOATS + w * WWIN; // this warp's data window

    // ---- async stage of this thread's horizontal tap entry (overlaps Stage A) ----
    {
        const Tap6* src = &g_taph[box][min(q, OUTSZ - 1)];
        unsigned int s0 = (unsigned int)__cvta_generic_to_shared(tapslot);
        asm volatile("cp.async.ca.shared.global [%0], [%1], 16;\n" :: "r"(s0), "l"((const float4*)src + 0));
        asm volatile("cp.async.ca.shared.global [%0], [%1], 16;\n" :: "r"(s0 + 16), "l"((const float4*)src + 1));
        asm volatile("cp.async.ca.shared.global [%0], [%1], 16;\n" :: "r"(s0 + 32), "l"((const float4*)src + 2));
        asm volatile("cp.async.commit_group;\n" ::: "memory");
    }

    // ---- vertical taps (broadcast 48B) + box meta ----
    const float4* tv4 = (const float4*)&g_tapv[box][p];
    const float4 v0 = __ldg(tv4 + 0);
    const float4 v1 = __ldg(tv4 + 1);
    const float4 v2 = __ldg(tv4 + 2);
    const float wh0 = v0.x, wh1 = v0.y, wh2 = v0.z, wh3 = v0.w, wh4 = v1.x, wh5 = v1.y;
    const int r0 = __float_as_int(v1.z) * (IMGW * 3 / 4);
    const int r1 = __float_as_int(v1.w) * (IMGW * 3 / 4);
    const int r2 = __float_as_int(v2.x) * (IMGW * 3 / 4);
    const int r3 = __float_as_int(v2.y) * (IMGW * 3 / 4);
    const int r4 = __float_as_int(v2.z) * (IMGW * 3 / 4);
    const int r5 = __float_as_int(v2.w) * (IMGW * 3 / 4);
    const float4* img4 = (const float4*)img;

    const int gbeg = __ldg(&g_gbeg[box]);
    const int cw   = __ldg(&g_cw[box]);

    // ---- this warp's input window [jmin, jend) — same FP exprs as precompute ----
    const float scw = (float)cw / (float)OUTSZ;
    const int qhi = min(qlo + 31, OUTSZ - 1);
    const float srclo = ((float)qlo + 0.5f) * scw - 0.5f;
    const float srchi = ((float)qhi + 0.5f) * scw - 0.5f;
    const int jmin = min(max((int)floorf(srclo) - 2, 0), cw - 1);
    const int jend = min(max((int)floorf(srchi) + 3, 0), cw - 1) + 1;  // exclusive

    const int fbeg = gbeg + jmin * 3;
    const int fend = gbeg + jend * 3;
    const int fb4  = fbeg & ~3;

    // ---- Stage A: vertical combine into this warp's private smem window ----
#pragma unroll 1
    for (int g = fb4 + 4 * lane; g < fend; g += 128) {
        const int g4 = g >> 2;
        float4 a0 = __ldg(img4 + r0 + g4);
        float4 a1 = __ldg(img4 + r1 + g4);
        float4 a2 = __ldg(img4 + r2 + g4);
        float4 a3 = __ldg(img4 + r3 + g4);
        float4 a4 = __ldg(img4 + r4 + g4);
        float4 a5 = __ldg(img4 + r5 + g4);
        float4 acc;
        acc.x = wh0 * a0.x; acc.y = wh0 * a0.y; acc.z = wh0 * a0.z; acc.w = wh0 * a0.w;
        acc.x = fmaf(wh1, a1.x, acc.x); acc.y = fmaf(wh1, a1.y, acc.y); acc.z = fmaf(wh1, a1.z, acc.z); acc.w = fmaf(wh1, a1.w, acc.w);
        acc.x = fmaf(wh2, a2.x, acc.x); acc.y = fmaf(wh2, a2.y, acc.y); acc.z = fmaf(wh2, a2.z, acc.z); acc.w = fmaf(wh2, a2.w, acc.w);
        acc.x = fmaf(wh3, a3.x, acc.x); acc.y = fmaf(wh3, a3.y, acc.y); acc.z = fmaf(wh3, a3.z, acc.z); acc.w = fmaf(wh3, a3.w, acc.w);
        acc.x = fmaf(wh4, a4.x, acc.x); acc.y = fmaf(wh4, a4.y, acc.y); acc.z = fmaf(wh4, a4.z, acc.z); acc.w = fmaf(wh4, a4.w, acc.w);
        acc.x = fmaf(wh5, a5.x, acc.x); acc.y = fmaf(wh5, a5.y, acc.y); acc.z = fmaf(wh5, a5.z, acc.z); acc.w = fmaf(wh5, a5.w, acc.w);
        *(float4*)(seg + (g - fb4)) = acc;   // aligned STS.128
    }

    asm volatile("cp.async.wait_group 0;\n" ::: "memory");
    __syncwarp();

    // ---- Stage B: horizontal combine, taps + data from smem ----
    if (q < OUTSZ) {
        const float4 h0 = *(const float4*)(tapslot + 0);  // w0..w3
        const float4 h1 = *(const float4*)(tapslot + 4);  // w4, w5, j0, j1
        const float4 h2 = *(const float4*)(tapslot + 8);  // j2..j5
        const float w0 = h0.x, w1 = h0.y, w2 = h0.z, w3 = h0.w, w4 = h1.x, w5 = h1.y;
        const int off = fb4 - gbeg;                       // seg offset of crop-local float 0
        const int j0 = __float_as_int(h1.z) - off, j1 = __float_as_int(h1.w) - off;
        const int j2 = __float_as_int(h2.x) - off, j3 = __float_as_int(h2.y) - off;
        const int j4 = __float_as_int(h2.z) - off, j5 = __float_as_int(h2.w) - off;

        float o0, o1, o2;
        o0 = w0 * seg[j0 + 0]; o1 = w0 * seg[j0 + 1]; o2 = w0 * seg[j0 + 2];
        o0 = fmaf(w1, seg[j1 + 0], o0); o1 = fmaf(w1, seg[j1 + 1], o1); o2 = fmaf(w1, seg[j1 + 2], o2);
        o0 = fmaf(w2, seg[j2 + 0], o0); o1 = fmaf(w2, seg[j2 + 1], o1); o2 = fmaf(w2, seg[j2 + 2], o2);
        o0 = fmaf(w3, seg[j3 + 0], o0); o1 = fmaf(w3, seg[j3 + 1], o1); o2 = fmaf(w3, seg[j3 + 2], o2);
        o0 = fmaf(w4, seg[j4 + 0], o0); o1 = fmaf(w4, seg[j4 + 1], o1); o2 = fmaf(w4, seg[j4 + 2], o2);
        o0 = fmaf(w5, seg[j5 + 0], o0); o1 = fmaf(w5, seg[j5 + 1], o1); o2 = fmaf(w5, seg[j5 + 2], o2);

        size_t oidx = (((size_t)box * OUTSZ + p) * OUTSZ + q) * 3;
        out[oidx + 0] = o0;
        out[oidx + 1] = o1;
        out[oidx + 2] = o2;
    }
}

extern "C" void kernel_launch(void* const* d_in, const int* in_sizes, int n_in,
                              void* d_out, int out_size) {
    const float* scores = (const float*)d_in[0];   // (100,)
    const float* boxes  = (const float*)d_in[1];   // (100,4)
    const float* img    = (const float*)d_in[2];   // (1,2048,2048,3)
    float* out = (float*)d_out;                    // (10,260,260,3)

    precompute_taps<<<NBOX, OUTSZ>>>(scores, boxes);

    dim3 grid(OUTSZ, NBOX);
    dim3 block(NTHR);
    size_t smem = SMEM_FLOATS * sizeof(float);     // ~42.6 KB

    // PDL launch: main kernel blocks may start while precompute is in flight.
    cudaLaunchConfig_t cfg = {};
    cfg.gridDim = grid;
    cfg.blockDim = block;
    cfg.dynamicSmemBytes = smem;
    cfg.stream = 0;
    cudaLaunchAttribute attrs[1];
    attrs[0].id = cudaLaunchAttributeProgrammaticStreamSerialization;
    attrs[0].val.programmaticStreamSerializationAllowed = 1;
    cfg.attrs = attrs;
    cfg.numAttrs = 1;

    cudaError_t err = cudaLaunchKernelEx(&cfg, crop_resize_kernel, img, out);
    if (err != cudaSuccess) {
        crop_resize_kernel<<<grid, block, smem>>>(img, out);
    }
}

// round 14
// speedup vs baseline: 1.1333x; 1.1333x over previous
#include <cuda_runtime.h>
#include <cstdint>
#include <math.h>

#define OUTSZ 260
#define IMGW  2048
#define IMGH  2048
#define TAPS  6
#define NBOX  10
#define NWARP 9
#define NTHR  (NWARP * 32)
#define WWIN  800   // floats per warp segment (worst case ~759)

struct __align__(16) Tap6 {
    float w[TAPS];
    int   j[TAPS];
};

__device__ Tap6  g_tapv[NBOX][OUTSZ];   // vertical: j = absolute image row
__device__ int   g_gbeg[NBOX];          // x0*3
__device__ int   g_cw[NBOX];            // cw
__device__ float g_valid[NBOX];         // 1.0f or 0.0f

// Lanczos3 weights for 6 integer-spaced taps (frac in [0,1)) via angle addition.
__device__ __forceinline__ void lanczos6(float frac, float* w) {
    const float sn = sinpif(frac);
    const float su = sinpif(frac * (1.0f / 3.0f));
    const float cu = cospif(frac * (1.0f / 3.0f));
    const float R3 = 0.8660254037844386f;
    float s3[TAPS];
    s3[0] = fmaf(su, -0.5f,  cu *  R3);
    s3[1] = fmaf(su,  0.5f,  cu *  R3);
    s3[2] = su;
    s3[3] = fmaf(su,  0.5f,  cu * -R3);
    s3[4] = fmaf(su, -0.5f,  cu * -R3);
    s3[5] = -su;
    const float C = 3.0f / (3.14159265358979323846f * 3.14159265358979323846f);
#pragma unroll
    for (int a = 0; a < TAPS; a++) {
        float d = frac + (float)(2 - a);
        float sgn = (a & 1) ? -sn : sn;
        float val = sgn * s3[a] * C / (d * d);
        w[a] = (fabsf(d) < 1e-8f) ? 1.0f : val;
    }
}

__global__ void precompute_taps(const float* __restrict__ scores,
                                const float* __restrict__ boxes) {
    const int box = blockIdx.x;     // 0..9
    const int p   = threadIdx.x;    // 0..259

    const float b0 = boxes[box * 4 + 0];
    const float b1 = boxes[box * 4 + 1];
    const float b2 = boxes[box * 4 + 2];
    const float b3 = boxes[box * 4 + 3];
    // XLA f32->s32 convert truncates toward zero; values non-negative here.
    const int y0 = (int)(b0 * (float)IMGH);
    const int x0 = (int)(b1 * (float)IMGW);
    const int y1 = (int)(b2 * (float)IMGH);
    const int x1 = (int)(b3 * (float)IMGW);
    const int ch = max(y1 - y0, 1);
    const int cw = max(x1 - x0, 1);

    const bool valid = (scores[0] >= 0.8f) && (scores[box] >= 0.8f) &&
                       (b1 >= 0.0f) && (b3 <= 1.0f);

    // vertical taps for output row p
    const float src = ((float)p + 0.5f) * ((float)ch / (float)OUTSZ) - 0.5f;
    const float f = floorf(src);
    const int base = (int)f - 2;
    Tap6 t;
    lanczos6(src - f, t.w);
    float s = t.w[0] + t.w[1] + t.w[2] + t.w[3] + t.w[4] + t.w[5];
    float inv = 1.0f / s;
#pragma unroll
    for (int a = 0; a < TAPS; a++) {
        t.w[a] *= inv;
        t.j[a] = min(max(base + a, 0), ch - 1) + y0;
    }
    g_tapv[box][p] = t;

    if (p == 0) {
        g_gbeg[box]  = x0 * 3;
        g_cw[box]    = cw;
        g_valid[box] = valid ? 1.0f : 0.0f;
    }
}

__global__ __launch_bounds__(NTHR, 3)
void crop_resize_kernel(const float* __restrict__ img,
                        float* __restrict__ out) {
    // PDL: wait until the precompute kernel's writes are visible.
    asm volatile("griddepcontrol.wait;" ::: "memory");

    const int p    = blockIdx.x;        // output row 0..259
    const int box  = blockIdx.y;        // 0..9
    const int w    = threadIdx.x >> 5;  // warp 0..8
    const int lane = threadIdx.x & 31;
    const int qlo  = w * 32;            // this warp's output columns [qlo, qlo+32)

    // ---- vertical taps (broadcast 48B) + box meta ----
    const float4* tv4 = (const float4*)&g_tapv[box][p];
    const float4 v0 = __ldg(tv4 + 0);
    const float4 v1 = __ldg(tv4 + 1);
    const float4 v2 = __ldg(tv4 + 2);
    const float wh0 = v0.x, wh1 = v0.y, wh2 = v0.z, wh3 = v0.w, wh4 = v1.x, wh5 = v1.y;
    // row offsets in float4 units (row * 6144 / 4)
    const int r0 = __float_as_int(v1.z) * (IMGW * 3 / 4);
    const int r1 = __float_as_int(v1.w) * (IMGW * 3 / 4);
    const int r2 = __float_as_int(v2.x) * (IMGW * 3 / 4);
    const int r3 = __float_as_int(v2.y) * (IMGW * 3 / 4);
    const int r4 = __float_as_int(v2.z) * (IMGW * 3 / 4);
    const int r5 = __float_as_int(v2.w) * (IMGW * 3 / 4);
    const float4* img4 = (const float4*)img;

    const int gbeg  = __ldg(&g_gbeg[box]);
    const int cw    = __ldg(&g_cw[box]);
    const float vld = __ldg(&g_valid[box]);

    // ---- this warp's input window [jmin, jend) in crop-local columns ----
    // Same FP expressions as Stage B below so clamped taps always land inside.
    const float scw = (float)cw / (float)OUTSZ;
    const int qhi = min(qlo + 31, OUTSZ - 1);
    const float srclo = ((float)qlo + 0.5f) * scw - 0.5f;
    const float srchi = ((float)qhi + 0.5f) * scw - 0.5f;
    const int jmin = min(max((int)floorf(srclo) - 2, 0), cw - 1);
    const int jend = min(max((int)floorf(srchi) + 3, 0), cw - 1) + 1;  // exclusive

    extern __shared__ float smem[];
    float* seg = smem + w * WWIN;

    const int fbeg = gbeg + jmin * 3;    // global float index of window start
    const int fend = gbeg + jend * 3;
    const int fb4  = fbeg & ~3;

    // ---- Stage A: software-pipelined x2 — 12 independent LDG.128 in flight ----
#pragma unroll 1
    for (int g = fb4 + 4 * lane; g < fend; g += 256) {
        const int g4 = g >> 2;
        const int gB = g + 128;
        const bool hasB = gB < fend;
        const int g4B = hasB ? (gB >> 2) : g4;

        // issue all 12 loads back-to-back (independent, fill LSU queue)
        float4 a0 = __ldg(img4 + r0 + g4);
        float4 a1 = __ldg(img4 + r1 + g4);
        float4 a2 = __ldg(img4 + r2 + g4);
        float4 a3 = __ldg(img4 + r3 + g4);
        float4 a4 = __ldg(img4 + r4 + g4);
        float4 a5 = __ldg(img4 + r5 + g4);
        float4 b0 = __ldg(img4 + r0 + g4B);
        float4 b1 = __ldg(img4 + r1 + g4B);
        float4 b2 = __ldg(img4 + r2 + g4B);
        float4 b3 = __ldg(img4 + r3 + g4B);
        float4 b4 = __ldg(img4 + r4 + g4B);
        float4 b5 = __ldg(img4 + r5 + g4B);

        float4 acc;
        acc.x = wh0 * a0.x; acc.y = wh0 * a0.y; acc.z = wh0 * a0.z; acc.w = wh0 * a0.w;
        acc.x = fmaf(wh1, a1.x, acc.x); acc.y = fmaf(wh1, a1.y, acc.y); acc.z = fmaf(wh1, a1.z, acc.z); acc.w = fmaf(wh1, a1.w, acc.w);
        acc.x = fmaf(wh2, a2.x, acc.x); acc.y = fmaf(wh2, a2.y, acc.y); acc.z = fmaf(wh2, a2.z, acc.z); acc.w = fmaf(wh2, a2.w, acc.w);
        acc.x = fmaf(wh3, a3.x, acc.x); acc.y = fmaf(wh3, a3.y, acc.y); acc.z = fmaf(wh3, a3.z, acc.z); acc.w = fmaf(wh3, a3.w, acc.w);
        acc.x = fmaf(wh4, a4.x, acc.x); acc.y = fmaf(wh4, a4.y, acc.y); acc.z = fmaf(wh4, a4.z, acc.z); acc.w = fmaf(wh4, a4.w, acc.w);
        acc.x = fmaf(wh5, a5.x, acc.x); acc.y = fmaf(wh5, a5.y, acc.y); acc.z = fmaf(wh5, a5.z, acc.z); acc.w = fmaf(wh5, a5.w, acc.w);
        *(float4*)(seg + (g - fb4)) = acc;

        if (hasB) {
            float4 accB;
            accB.x = wh0 * b0.x; accB.y = wh0 * b0.y; accB.z = wh0 * b0.z; accB.w = wh0 * b0.w;
            accB.x = fmaf(wh1, b1.x, accB.x); accB.y = fmaf(wh1, b1.y, accB.y); accB.z = fmaf(wh1, b1.z, accB.z); accB.w = fmaf(wh1, b1.w, accB.w);
            accB.x = fmaf(wh2, b2.x, accB.x); accB.y = fmaf(wh2, b2.y, accB.y); accB.z = fmaf(wh2, b2.z, accB.z); accB.w = fmaf(wh2, b2.w, accB.w);
            accB.x = fmaf(wh3, b3.x, accB.x); accB.y = fmaf(wh3, b3.y, accB.y); accB.z = fmaf(wh3, b3.z, accB.z); accB.w = fmaf(wh3, b3.w, accB.w);
            accB.x = fmaf(wh4, b4.x, accB.x); accB.y = fmaf(wh4, b4.y, accB.y); accB.z = fmaf(wh4, b4.z, accB.z); accB.w = fmaf(wh4, b4.w, accB.w);
            accB.x = fmaf(wh5, b5.x, accB.x); accB.y = fmaf(wh5, b5.y, accB.y); accB.z = fmaf(wh5, b5.z, accB.z); accB.w = fmaf(wh5, b5.w, accB.w);
            *(float4*)(seg + (gB - fb4)) = accB;
        }
    }
    __syncwarp();

    // ---- Stage B: horizontal combine from this warp's window ----
    const int q = qlo + lane;
    if (q < OUTSZ) {
        // crop-local float index j*3 lives at seg[j*3 - (fb4 - gbeg)]
        const float* rcB = seg - (fb4 - gbeg);
        const float src = ((float)q + 0.5f) * scw - 0.5f;
        const float f = floorf(src);
        const int base = (int)f - 2;
        float ww[TAPS];
        lanczos6(src - f, ww);
        float sw = ww[0] + ww[1] + ww[2] + ww[3] + ww[4] + ww[5];
        const float invw = vld / sw;             // fold validity mask

        float o0 = 0.0f, o1 = 0.0f, o2 = 0.0f;
#pragma unroll
        for (int b = 0; b < TAPS; b++) {
            float wgt = ww[b] * invw;
            int j = min(max(base + b, 0), cw - 1) * 3;
            o0 = fmaf(wgt, rcB[j + 0], o0);
            o1 = fmaf(wgt, rcB[j + 1], o1);
            o2 = fmaf(wgt, rcB[j + 2], o2);
        }
        size_t oidx = (((size_t)box * OUTSZ + p) * OUTSZ + q) * 3;
        out[oidx + 0] = o0;
        out[oidx + 1] = o1;
        out[oidx + 2] = o2;
    }
}

extern "C" void kernel_launch(void* const* d_in, const int* in_sizes, int n_in,
                              void* d_out, int out_size) {
    const float* scores = (const float*)d_in[0];   // (100,)
    const float* boxes  = (const float*)d_in[1];   // (100,4)
    const float* img    = (const float*)d_in[2];   // (1,2048,2048,3)
    float* out = (float*)d_out;                    // (10,260,260,3)

    precompute_taps<<<NBOX, OUTSZ>>>(scores, boxes);

    dim3 grid(OUTSZ, NBOX);
    dim3 block(NTHR);
    size_t smem = (size_t)NWARP * WWIN * sizeof(float);  // 28.8 KB

    // PDL launch: main kernel blocks may start while precompute is in flight.
    cudaLaunchConfig_t cfg = {};
    cfg.gridDim = grid;
    cfg.blockDim = block;
    cfg.dynamicSmemBytes = smem;
    cfg.stream = 0;
    cudaLaunchAttribute attrs[1];
    attrs[0].id = cudaLaunchAttributeProgrammaticStreamSerialization;
    attrs[0].val.programmaticStreamSerializationAllowed = 1;
    cfg.attrs = attrs;
    cfg.numAttrs = 1;

    cudaError_t err = cudaLaunchKernelEx(&cfg, crop_resize_kernel, img, out);
    if (err != cudaSuccess) {
        // Fallback: plain serialized launch (griddepcontrol.wait is a no-op).
        crop_resize_kernel<<<grid, block, smem>>>(img, out);
    }
}

// round 15
// speedup vs baseline: 1.2273x; 1.0830x over previous
#include <cuda_runtime.h>
#include <cstdint>
#include <math.h>

#define OUTSZ 260
#define IMGW  2048
#define IMGH  2048
#define TAPS  6
#define NBOX  10
#define NWARP 9
#define NTHR  (NWARP * 32)
#define WWIN  800   // floats per warp segment (worst case ~759)

struct __align__(16) Tap6 {
    float w[TAPS];
    int   j[TAPS];
};

__device__ Tap6  g_tapv[NBOX][OUTSZ];   // vertical: j = absolute image row
__device__ int   g_gbeg[NBOX];          // x0*3
__device__ int   g_cw[NBOX];            // cw
__device__ float g_valid[NBOX];         // 1.0f or 0.0f

__device__ __forceinline__ float frcp(float x) {
    float r; asm("rcp.approx.f32 %0, %1;" : "=f"(r) : "f"(x)); return r;
}

// Lanczos3 weights for 6 integer-spaced taps, division-free:
//   d_a = frac + (2 - a); 1/d_a via prefix/suffix products + ONE rcp.approx.
//   frac clamped to [1e-6, 1) so no d is exactly 0 (weights are normalized,
//   so the ~1e-6 perturbation is far below the 1e-3 tolerance).
__device__ __forceinline__ void lanczos6(float frac, float* w) {
    frac = fmaxf(frac, 1e-6f);
    const float sn = sinpif(frac);
    const float su = sinpif(frac * (1.0f / 3.0f));
    const float cu = cospif(frac * (1.0f / 3.0f));
    const float R3 = 0.8660254037844386f;
    float s3[TAPS];
    s3[0] = fmaf(su, -0.5f,  cu *  R3);
    s3[1] = fmaf(su,  0.5f,  cu *  R3);
    s3[2] = su;
    s3[3] = fmaf(su,  0.5f,  cu * -R3);
    s3[4] = fmaf(su, -0.5f,  cu * -R3);
    s3[5] = -su;

    const float d0 = frac + 2.0f, d1 = frac + 1.0f, d2 = frac;
    const float d3 = frac - 1.0f, d4 = frac - 2.0f, d5 = frac - 3.0f;
    // prefix products
    const float p01 = d0 * d1, p012 = p01 * d2, p0123 = p012 * d3, p01234 = p0123 * d4;
    // suffix products
    const float s45 = d4 * d5, s345 = d3 * s45, s2345 = d2 * s345, s12345 = d1 * s2345;
    const float P  = p01234 * d5;
    const float rp = frcp(P);
    const float i0 = s12345 * rp;         // 1/d0
    const float i1 = (d0 * s2345) * rp;   // 1/d1
    const float i2 = (p01 * s345) * rp;   // 1/d2
    const float i3 = (p012 * s45) * rp;   // 1/d3
    const float i4 = (p0123 * d5) * rp;   // 1/d4
    const float i5 = p01234 * rp;         // 1/d5

    const float C = 3.0f / (3.14159265358979323846f * 3.14159265358979323846f);
    const float snC = sn * C;
    w[0] =  snC * s3[0] * (i0 * i0);
    w[1] = -snC * s3[1] * (i1 * i1);
    w[2] =  snC * s3[2] * (i2 * i2);
    w[3] = -snC * s3[3] * (i3 * i3);
    w[4] =  snC * s3[4] * (i4 * i4);
    w[5] = -snC * s3[5] * (i5 * i5);
}

__global__ void precompute_taps(const float* __restrict__ scores,
                                const float* __restrict__ boxes) {
    const int box = blockIdx.x;     // 0..9
    const int p   = threadIdx.x;    // 0..259

    const float b0 = boxes[box * 4 + 0];
    const float b1 = boxes[box * 4 + 1];
    const float b2 = boxes[box * 4 + 2];
    const float b3 = boxes[box * 4 + 3];
    // XLA f32->s32 convert truncates toward zero; values non-negative here.
    const int y0 = (int)(b0 * (float)IMGH);
    const int x0 = (int)(b1 * (float)IMGW);
    const int y1 = (int)(b2 * (float)IMGH);
    const int x1 = (int)(b3 * (float)IMGW);
    const int ch = max(y1 - y0, 1);
    const int cw = max(x1 - x0, 1);

    const bool valid = (scores[0] >= 0.8f) && (scores[box] >= 0.8f) &&
                       (b1 >= 0.0f) && (b3 <= 1.0f);

    // vertical taps for output row p
    const float src = ((float)p + 0.5f) * ((float)ch / (float)OUTSZ) - 0.5f;
    const float f = floorf(src);
    const int base = (int)f - 2;
    Tap6 t;
    lanczos6(src - f, t.w);
    float s = t.w[0] + t.w[1] + t.w[2] + t.w[3] + t.w[4] + t.w[5];
    float inv = frcp(s);
#pragma unroll
    for (int a = 0; a < TAPS; a++) {
        t.w[a] *= inv;
        t.j[a] = min(max(base + a, 0), ch - 1) + y0;
    }
    g_tapv[box][p] = t;

    if (p == 0) {
        g_gbeg[box]  = x0 * 3;
        g_cw[box]    = cw;
        g_valid[box] = valid ? 1.0f : 0.0f;
    }
}

__global__ __launch_bounds__(NTHR, 4)
void crop_resize_kernel(const float* __restrict__ img,
                        float* __restrict__ out) {
    // PDL: wait until the precompute kernel's writes are visible.
    asm volatile("griddepcontrol.wait;" ::: "memory");

    const int p    = blockIdx.x;        // output row 0..259
    const int box  = blockIdx.y;        // 0..9
    const int w    = threadIdx.x >> 5;  // warp 0..8
    const int lane = threadIdx.x & 31;
    const int qlo  = w * 32;            // this warp's output columns [qlo, qlo+32)

    // ---- vertical taps (broadcast 48B) + box meta ----
    const float4* tv4 = (const float4*)&g_tapv[box][p];
    const float4 v0 = __ldg(tv4 + 0);
    const float4 v1 = __ldg(tv4 + 1);
    const float4 v2 = __ldg(tv4 + 2);
    const float wh0 = v0.x, wh1 = v0.y, wh2 = v0.z, wh3 = v0.w, wh4 = v1.x, wh5 = v1.y;
    // row offsets in float4 units (row * 6144 / 4)
    const int r0 = __float_as_int(v1.z) * (IMGW * 3 / 4);
    const int r1 = __float_as_int(v1.w) * (IMGW * 3 / 4);
    const int r2 = __float_as_int(v2.x) * (IMGW * 3 / 4);
    const int r3 = __float_as_int(v2.y) * (IMGW * 3 / 4);
    const int r4 = __float_as_int(v2.z) * (IMGW * 3 / 4);
    const int r5 = __float_as_int(v2.w) * (IMGW * 3 / 4);
    const float4* img4 = (const float4*)img;

    const int gbeg  = __ldg(&g_gbeg[box]);
    const int cw    = __ldg(&g_cw[box]);
    const float vld = __ldg(&g_valid[box]);

    // ---- this warp's input window [jmin, jend) in crop-local columns ----
    // Same FP expressions as Stage B below so clamped taps always land inside.
    const float scw = (float)cw / (float)OUTSZ;
    const int qhi = min(qlo + 31, OUTSZ - 1);
    const float srclo = ((float)qlo + 0.5f) * scw - 0.5f;
    const float srchi = ((float)qhi + 0.5f) * scw - 0.5f;
    const int jmin = min(max((int)floorf(srclo) - 2, 0), cw - 1);
    const int jend = min(max((int)floorf(srchi) + 3, 0), cw - 1) + 1;  // exclusive

    extern __shared__ float smem[];
    float* seg = smem + w * WWIN;

    const int fbeg = gbeg + jmin * 3;    // global float index of window start
    const int fend = gbeg + jend * 3;
    const int fb4  = fbeg & ~3;

    // ---- Stage A: vertical combine into this warp's private smem window ----
#pragma unroll 1
    for (int g = fb4 + 4 * lane; g < fend; g += 128) {
        const int g4 = g >> 2;
        float4 a0 = __ldg(img4 + r0 + g4);
        float4 a1 = __ldg(img4 + r1 + g4);
        float4 a2 = __ldg(img4 + r2 + g4);
        float4 a3 = __ldg(img4 + r3 + g4);
        float4 a4 = __ldg(img4 + r4 + g4);
        float4 a5 = __ldg(img4 + r5 + g4);
        float4 acc;
        acc.x = wh0 * a0.x; acc.y = wh0 * a0.y; acc.z = wh0 * a0.z; acc.w = wh0 * a0.w;
        acc.x = fmaf(wh1, a1.x, acc.x); acc.y = fmaf(wh1, a1.y, acc.y); acc.z = fmaf(wh1, a1.z, acc.z); acc.w = fmaf(wh1, a1.w, acc.w);
        acc.x = fmaf(wh2, a2.x, acc.x); acc.y = fmaf(wh2, a2.y, acc.y); acc.z = fmaf(wh2, a2.z, acc.z); acc.w = fmaf(wh2, a2.w, acc.w);
        acc.x = fmaf(wh3, a3.x, acc.x); acc.y = fmaf(wh3, a3.y, acc.y); acc.z = fmaf(wh3, a3.z, acc.z); acc.w = fmaf(wh3, a3.w, acc.w);
        acc.x = fmaf(wh4, a4.x, acc.x); acc.y = fmaf(wh4, a4.y, acc.y); acc.z = fmaf(wh4, a4.z, acc.z); acc.w = fmaf(wh4, a4.w, acc.w);
        acc.x = fmaf(wh5, a5.x, acc.x); acc.y = fmaf(wh5, a5.y, acc.y); acc.z = fmaf(wh5, a5.z, acc.z); acc.w = fmaf(wh5, a5.w, acc.w);
        *(float4*)(seg + (g - fb4)) = acc;   // aligned STS.128
    }
    __syncwarp();

    // ---- Stage B: horizontal combine from this warp's window ----
    const int q = qlo + lane;
    if (q < OUTSZ) {
        // crop-local float index j*3 lives at seg[j*3 - (fb4 - gbeg)]
        const float* rcB = seg - (fb4 - gbeg);
        const float src = ((float)q + 0.5f) * scw - 0.5f;
        const float f = floorf(src);
        const int base = (int)f - 2;
        float ww[TAPS];
        lanczos6(src - f, ww);
        float sw = ww[0] + ww[1] + ww[2] + ww[3] + ww[4] + ww[5];
        const float invw = vld * frcp(sw);       // fold validity mask, no division

        float o0 = 0.0f, o1 = 0.0f, o2 = 0.0f;
#pragma unroll
        for (int b = 0; b < TAPS; b++) {
            float wgt = ww[b] * invw;
            int j = min(max(base + b, 0), cw - 1) * 3;
            o0 = fmaf(wgt, rcB[j + 0], o0);
            o1 = fmaf(wgt, rcB[j + 1], o1);
            o2 = fmaf(wgt, rcB[j + 2], o2);
        }
        size_t oidx = (((size_t)box * OUTSZ + p) * OUTSZ + q) * 3;
        out[oidx + 0] = o0;
        out[oidx + 1] = o1;
        out[oidx + 2] = o2;
    }
}

extern "C" void kernel_launch(void* const* d_in, const int* in_sizes, int n_in,
                              void* d_out, int out_size) {
    const float* scores = (const float*)d_in[0];   // (100,)
    const float* boxes  = (const float*)d_in[1];   // (100,4)
    const float* img    = (const float*)d_in[2];   // (1,2048,2048,3)
    float* out = (float*)d_out;                    // (10,260,260,3)

    precompute_taps<<<NBOX, OUTSZ>>>(scores, boxes);

    dim3 grid(OUTSZ, NBOX);
    dim3 block(NTHR);
    size_t smem = (size_t)NWARP * WWIN * sizeof(float);  // 28.8 KB

    // PDL launch: main kernel blocks may start while precompute is in flight.
    cudaLaunchConfig_t cfg = {};
    cfg.gridDim = grid;
    cfg.blockDim = block;
    cfg.dynamicSmemBytes = smem;
    cfg.stream = 0;
    cudaLaunchAttribute attrs[1];
    attrs[0].id = cudaLaunchAttributeProgrammaticStreamSerialization;
    attrs[0].val.programmaticStreamSerializationAllowed = 1;
    cfg.attrs = attrs;
    cfg.numAttrs = 1;

    cudaError_t err = cudaLaunchKernelEx(&cfg, crop_resize_kernel, img, out);
    if (err != cudaSuccess) {
        // Fallback: plain serialized launch (griddepcontrol.wait is a no-op).
        crop_resize_kernel<<<grid, block, smem>>>(img, out);
    }
}